// round 4
// baseline (speedup 1.0000x reference)
#include <cuda_runtime.h>
#include <cuda_bf16.h>
#include <cstdint>

// SpikeEncoder: rates = sigmoid(x @ W^T + b); spikes = (u < rates)
// x: [256,512] f32, W: [2048,512] f32, b: [2048] f32, u: [256,100,2048] f32
// out: spikes [256*100*2048] f32, then rates [256*2048] f32

#define BATCH 256
#define INPUT_DIM 512
#define NUM_NEURONS 2048
#define TIME_STEPS 100

#define TBM 32
#define TBN 64
#define TBK 32
#define NTILES (INPUT_DIM / TBK)   // 16

// Spike kernel blocking: each block = 20 timesteps of one batch row.
#define TCH 20                     // timesteps per block (100/20 = 5 chunks)
#define PFT 10                     // timesteps prefetched into L2 pre-sync
                                   // 1280 blocks * 10*8KB = 100 MB (< L2 126MB)

__device__ __forceinline__ void cp_async16(uint32_t smem_addr, const void* gmem) {
    asm volatile("cp.async.cg.shared.global [%0], [%1], 16;\n"
                 :: "r"(smem_addr), "l"(gmem));
}
__device__ __forceinline__ void cp_commit() {
    asm volatile("cp.async.commit_group;\n" ::: "memory");
}
__device__ __forceinline__ void cp_wait0() {
    asm volatile("cp.async.wait_group 0;\n" ::: "memory");
}

// ---------------------------------------------------------------------------
// Kernel A: tiled fp32 GEMM (C = x @ W^T + b) -> sigmoid -> rates
// BM=32 x BN=64, 128 threads, 4x4 micro-tile, grid (32,8)=256 blocks so the
// whole chip is used (~2 blocks/SM, 8 warps/SM of issue slack).
// Row-major smem with XOR chunk swizzle, cp.async double-buffered.
// PDL trigger at kernel START: the spike grid launches concurrently and
// prefetches u into L2 on otherwise-idle DRAM bandwidth.
// ---------------------------------------------------------------------------
__global__ __launch_bounds__(128)
void rates_kernel(const float* __restrict__ x,
                  const float* __restrict__ W,
                  const float* __restrict__ bias,
                  float* __restrict__ rates) {
#if __CUDA_ARCH__ >= 900
    cudaTriggerProgrammaticLaunchCompletion();
#endif
    __shared__ float As[2][TBM * TBK];   // 4KB x2
    __shared__ float Bs[2][TBN * TBK];   // 8KB x2

    const int tid   = threadIdx.x;
    const int nBase = blockIdx.x * TBN;
    const int mBase = blockIdx.y * TBM;

    const int m0 = (tid & 7) * 4;    // 8 groups x 4 = 32 batch rows
    const int n0 = (tid >> 3) * 4;   // 16 groups x 4 = 64 neurons

    // Cooperative-load coords. A: 256 float4/tile (2/thread); B: 512 (4/thread)
    int arw[2], ack[2], brw[4], bck[4];
    uint32_t dstA[2], dstB[4];
    const uint32_t sA = (uint32_t)__cvta_generic_to_shared(&As[0][0]);
    const uint32_t sB = (uint32_t)__cvta_generic_to_shared(&Bs[0][0]);
#pragma unroll
    for (int l = 0; l < 2; l++) {
        const int f = tid + l * 128;        // 0..255
        arw[l] = f >> 3; ack[l] = f & 7;
        const int sw = ack[l] ^ ((arw[l] >> 2) & 7);
        dstA[l] = sA + (uint32_t)(arw[l] * TBK + sw * 4) * 4u;
    }
#pragma unroll
    for (int l = 0; l < 4; l++) {
        const int f = tid + l * 128;        // 0..511
        brw[l] = f >> 3; bck[l] = f & 7;
        const int sw = bck[l] ^ ((brw[l] >> 2) & 7);
        dstB[l] = sB + (uint32_t)(brw[l] * TBK + sw * 4) * 4u;
    }
    const uint32_t bufA = (uint32_t)(TBM * TBK) * 4u;
    const uint32_t bufB = (uint32_t)(TBN * TBK) * 4u;

    // Prologue: tile 0 -> buffer 0
#pragma unroll
    for (int l = 0; l < 2; l++)
        cp_async16(dstA[l], &x[(mBase + arw[l]) * INPUT_DIM + ack[l] * 4]);
#pragma unroll
    for (int l = 0; l < 4; l++)
        cp_async16(dstB[l], &W[(nBase + brw[l]) * INPUT_DIM + bck[l] * 4]);
    cp_commit();

    float accL[4][4], accH[4][4];
#pragma unroll
    for (int i = 0; i < 4; i++)
#pragma unroll
        for (int j = 0; j < 4; j++) { accL[i][j] = 0.0f; accH[i][j] = 0.0f; }

    int aRow[4], aSwz[4], bRow[4], bSwz[4];
#pragma unroll
    for (int i = 0; i < 4; i++) {
        aRow[i] = (m0 + i) * TBK;  aSwz[i] = ((m0 + i) >> 2) & 7;
        bRow[i] = (n0 + i) * TBK;  bSwz[i] = ((n0 + i) >> 2) & 7;
    }

    for (int t = 0; t < NTILES; t++) {
        const int cur = t & 1;
        cp_wait0();
        __syncthreads();

        if (t < NTILES - 1) {
            const int k0 = (t + 1) * TBK;
            const uint32_t nb = (uint32_t)((t + 1) & 1);
#pragma unroll
            for (int l = 0; l < 2; l++)
                cp_async16(dstA[l] + nb * bufA,
                           &x[(mBase + arw[l]) * INPUT_DIM + k0 + ack[l] * 4]);
#pragma unroll
            for (int l = 0; l < 4; l++)
                cp_async16(dstB[l] + nb * bufB,
                           &W[(nBase + brw[l]) * INPUT_DIM + k0 + bck[l] * 4]);
            cp_commit();
        }

        const float* __restrict__ A = &As[cur][0];
        const float* __restrict__ B = &Bs[cur][0];

#pragma unroll
        for (int s = 0; s < 8; s++) {        // 4 k's per step
            float4 av[4], bv[4];
#pragma unroll
            for (int i = 0; i < 4; i++)
                av[i] = *(const float4*)&A[aRow[i] + ((s ^ aSwz[i]) << 2)];
#pragma unroll
            for (int j = 0; j < 4; j++)
                bv[j] = *(const float4*)&B[bRow[j] + ((s ^ bSwz[j]) << 2)];

#pragma unroll
            for (int i = 0; i < 4; i++)
#pragma unroll
                for (int j = 0; j < 4; j++) {
                    accL[i][j] = fmaf(av[i].x, bv[j].x, accL[i][j]);
                    accH[i][j] = fmaf(av[i].y, bv[j].y, accH[i][j]);
                    accL[i][j] = fmaf(av[i].z, bv[j].z, accL[i][j]);
                    accH[i][j] = fmaf(av[i].w, bv[j].w, accH[i][j]);
                }
        }
    }

    // Epilogue: bias + sigmoid
    const float4 bv4 = *(const float4*)&bias[nBase + n0];
    const float bb[4] = {bv4.x, bv4.y, bv4.z, bv4.w};
#pragma unroll
    for (int i = 0; i < 4; i++) {
        float4 o;
        float v[4];
#pragma unroll
        for (int j = 0; j < 4; j++) {
            const float z = (accL[i][j] + accH[i][j]) + bb[j];
            v[j] = 1.0f / (1.0f + expf(-z));
        }
        o.x = v[0]; o.y = v[1]; o.z = v[2]; o.w = v[3];
        *(float4*)&rates[(mBase + m0 + i) * NUM_NEURONS + nBase + n0] = o;
    }
}

// ---------------------------------------------------------------------------
// Kernel B: streaming spike compare with PDL L2 prefetch.
// grid (5, BATCH) = 1280 blocks, 256 threads; each block = 20 timesteps of
// one batch row (160 KB of u). Pre-sync: prefetch.global.L2 over the first
// 10 timesteps (100 MB chip-wide) so the stream phase hits L2 for ~half of u.
// Post-sync: rates into registers once, then 20 rows of ldcs/compare/stcs.
// ---------------------------------------------------------------------------
__global__ __launch_bounds__(256)
void spike_kernel(const float4* __restrict__ u,
                  const float4* __restrict__ rates,
                  float4* __restrict__ spikes) {
    const int b  = blockIdx.y;
    const int t0 = blockIdx.x * TCH;
    const long long rowBase = ((long long)b * TIME_STEPS + t0) * (NUM_NEURONS / 4);

    // Phase 1: L2 prefetch of the first PFT rows (runs during the GEMM).
    {
        const char* pbase = (const char*)(u + rowBase);
        const int nlines = PFT * NUM_NEURONS * 4 / 128;   // 640
#pragma unroll 1
        for (int l = threadIdx.x; l < nlines; l += 256)
            asm volatile("prefetch.global.L2 [%0];" :: "l"(pbase + (long long)l * 128));
    }

#if __CUDA_ARCH__ >= 900
    cudaGridDependencySynchronize();
#endif

    const int j = threadIdx.x * 2;
    const float4* rrow = rates + b * (NUM_NEURONS / 4);
    const float4 r0 = __ldg(&rrow[j]);
    const float4 r1 = __ldg(&rrow[j + 1]);

#pragma unroll 4
    for (int t = 0; t < TCH; t++) {
        const long long base = rowBase + (long long)t * (NUM_NEURONS / 4);
        const float4 u0 = __ldcs(&u[base + j]);
        const float4 u1 = __ldcs(&u[base + j + 1]);

        float4 s0, s1;
        s0.x = (u0.x < r0.x) ? 1.0f : 0.0f;
        s0.y = (u0.y < r0.y) ? 1.0f : 0.0f;
        s0.z = (u0.z < r0.z) ? 1.0f : 0.0f;
        s0.w = (u0.w < r0.w) ? 1.0f : 0.0f;
        s1.x = (u1.x < r1.x) ? 1.0f : 0.0f;
        s1.y = (u1.y < r1.y) ? 1.0f : 0.0f;
        s1.z = (u1.z < r1.z) ? 1.0f : 0.0f;
        s1.w = (u1.w < r1.w) ? 1.0f : 0.0f;

        __stcs(&spikes[base + j], s0);
        __stcs(&spikes[base + j + 1], s1);
    }
}

extern "C" void kernel_launch(void* const* d_in, const int* in_sizes, int n_in,
                              void* d_out, int out_size) {
    const float* x = (const float*)d_in[0];
    const float* W = (const float*)d_in[1];
    const float* b = (const float*)d_in[2];
    const float* u = (const float*)d_in[3];

    float* out    = (float*)d_out;
    float* spikes = out;                                               // 52,428,800
    float* rates  = out + (long long)BATCH * TIME_STEPS * NUM_NEURONS; // +524,288

    dim3 gridA(NUM_NEURONS / TBN, BATCH / TBM);   // (32, 8) = 256 blocks
    rates_kernel<<<gridA, 128>>>(x, W, b, rates);

    const float4* u4 = (const float4*)u;
    const float4* r4 = (const float4*)rates;
    float4*       s4 = (float4*)spikes;

    cudaLaunchConfig_t cfg = {};
    cfg.gridDim  = dim3(TIME_STEPS / TCH, BATCH, 1);   // (5, 256) = 1280 blocks
    cfg.blockDim = dim3(256, 1, 1);
    cfg.dynamicSmemBytes = 0;
    cfg.stream = 0;
    cudaLaunchAttribute attrs[1];
    attrs[0].id = cudaLaunchAttributeProgrammaticStreamSerialization;
    attrs[0].val.programmaticStreamSerializationAllowed = 1;
    cfg.attrs = attrs;
    cfg.numAttrs = 1;

    cudaError_t e = cudaLaunchKernelEx(&cfg, spike_kernel, u4, r4, s4);
    if (e != cudaSuccess) {
        (void)cudaGetLastError();  // clear
        spike_kernel<<<dim3(TIME_STEPS / TCH, BATCH, 1), 256>>>(u4, r4, s4);
    }
}

// round 5
// speedup vs baseline: 1.1314x; 1.1314x over previous
#include <cuda_runtime.h>
#include <cuda_bf16.h>
#include <cstdint>

// SpikeEncoder: rates = sigmoid(x @ W^T + b); spikes = (u < rates)
// x: [256,512] f32, W: [2048,512] f32, b: [2048] f32, u: [256,100,2048] f32
// out: spikes [256*100*2048] f32, then rates [256*2048] f32

#define BATCH 256
#define INPUT_DIM 512
#define NUM_NEURONS 2048
#define TIME_STEPS 100

#define TBM 64
#define TBN 64
#define TBK 32
#define NTILES (INPUT_DIM / TBK)   // 16

__device__ __forceinline__ void cp_async16(uint32_t smem_addr, const void* gmem) {
    asm volatile("cp.async.cg.shared.global [%0], [%1], 16;\n"
                 :: "r"(smem_addr), "l"(gmem));
}
__device__ __forceinline__ void cp_commit() {
    asm volatile("cp.async.commit_group;\n" ::: "memory");
}
__device__ __forceinline__ void cp_wait0() {
    asm volatile("cp.async.wait_group 0;\n" ::: "memory");
}

// Packed dual-FMA: acc.{lo,hi} += a.{lo,hi} * b.{lo,hi}  (one FFMA2 issue slot)
__device__ __forceinline__ void fma2(unsigned long long& acc,
                                     unsigned long long a,
                                     unsigned long long b) {
    asm("fma.rn.f32x2 %0, %1, %2, %0;" : "+l"(acc) : "l"(a), "l"(b));
}

// ---------------------------------------------------------------------------
// Kernel A: tiled fp32 GEMM (C = x @ W^T + b) -> sigmoid -> rates
// 128 threads, 8x4 micro-tile, XOR-swizzled row-major smem, cp.async
// double-buffered. Inner product uses packed f32x2 FMA (FFMA2): 2 fp32 FMA
// per issue slot -> halves the FFMA issue floor vs scalar FFMA (rt_SMSP=2
// uses only half the 128 FP32 units/SM). Accumulators packed: lo = k pairs
// {0,1 mod4}-ish, hi = {2,3} -> same dual-split accuracy as before.
// grid (32, 4).
// ---------------------------------------------------------------------------
__global__ __launch_bounds__(128)
void rates_kernel(const float* __restrict__ x,
                  const float* __restrict__ W,
                  const float* __restrict__ bias,
                  float* __restrict__ rates) {
    __shared__ float As[2][TBM * TBK];
    __shared__ float Bs[2][TBM * TBK];

    const int tid   = threadIdx.x;
    const int nBase = blockIdx.x * TBN;
    const int mBase = blockIdx.y * TBM;

    const int m0 = (tid & 7) * 8;    // 8 rows of A per thread
    const int n0 = (tid >> 3) * 4;   // 4 rows of B per thread

    // Cooperative-load coords: 512 float4 per matrix per tile, 4 per thread.
    int lr[4], lc[4];
    uint32_t dstA[4], dstB[4];
    const uint32_t sA = (uint32_t)__cvta_generic_to_shared(&As[0][0]);
    const uint32_t sB = (uint32_t)__cvta_generic_to_shared(&Bs[0][0]);
#pragma unroll
    for (int l = 0; l < 4; l++) {
        const int f = tid + l * 128;        // 0..511
        lr[l] = f >> 3;                     // row 0..63
        lc[l] = f & 7;                      // k-chunk 0..7
        const int sw = lc[l] ^ ((lr[l] >> 2) & 7);
        const uint32_t off = (uint32_t)(lr[l] * TBK + sw * 4) * 4u;
        dstA[l] = sA + off;
        dstB[l] = sB + off;
    }
    const uint32_t bufStride = (uint32_t)(TBM * TBK) * 4u;

    // Prologue: async-load tile 0 into buffer 0
#pragma unroll
    for (int l = 0; l < 4; l++) {
        cp_async16(dstA[l], &x[(mBase + lr[l]) * INPUT_DIM + lc[l] * 4]);
        cp_async16(dstB[l], &W[(nBase + lr[l]) * INPUT_DIM + lc[l] * 4]);
    }
    cp_commit();

    // Packed accumulators: acc[i][j] = (lo, hi) fp32 pair
    unsigned long long acc[8][4];
#pragma unroll
    for (int i = 0; i < 8; i++)
#pragma unroll
        for (int j = 0; j < 4; j++) acc[i][j] = 0ull;

    int aRow[8], aSwz[8], bRow[4], bSwz[4];
#pragma unroll
    for (int i = 0; i < 8; i++) {
        aRow[i] = (m0 + i) * TBK;
        aSwz[i] = ((m0 + i) >> 2) & 7;
    }
#pragma unroll
    for (int j = 0; j < 4; j++) {
        bRow[j] = (n0 + j) * TBK;
        bSwz[j] = ((n0 + j) >> 2) & 7;
    }

    for (int t = 0; t < NTILES; t++) {
        const int cur = t & 1;
        cp_wait0();
        __syncthreads();

        if (t < NTILES - 1) {
            const int k0 = (t + 1) * TBK;
            const uint32_t boff = (uint32_t)((t + 1) & 1) * bufStride;
#pragma unroll
            for (int l = 0; l < 4; l++) {
                cp_async16(dstA[l] + boff, &x[(mBase + lr[l]) * INPUT_DIM + k0 + lc[l] * 4]);
                cp_async16(dstB[l] + boff, &W[(nBase + lr[l]) * INPUT_DIM + k0 + lc[l] * 4]);
            }
            cp_commit();
        }

        const float* __restrict__ A = &As[cur][0];
        const float* __restrict__ B = &Bs[cur][0];

#pragma unroll
        for (int s = 0; s < 8; s++) {        // 4 k's per step (2 packed pairs)
            ulonglong2 av[8], bv[4];
#pragma unroll
            for (int i = 0; i < 8; i++)
                av[i] = *(const ulonglong2*)&A[aRow[i] + ((s ^ aSwz[i]) << 2)];
#pragma unroll
            for (int j = 0; j < 4; j++)
                bv[j] = *(const ulonglong2*)&B[bRow[j] + ((s ^ bSwz[j]) << 2)];

#pragma unroll
            for (int i = 0; i < 8; i++)
#pragma unroll
                for (int j = 0; j < 4; j++) {
                    fma2(acc[i][j], av[i].x, bv[j].x);
                    fma2(acc[i][j], av[i].y, bv[j].y);
                }
        }
    }

    // Epilogue: unpack (lo+hi) + bias + sigmoid, float4 stores
    const float4 bv4 = *(const float4*)&bias[nBase + n0];
    const float bb[4] = {bv4.x, bv4.y, bv4.z, bv4.w};
#pragma unroll
    for (int i = 0; i < 8; i++) {
        float4 o;
        float v[4];
#pragma unroll
        for (int j = 0; j < 4; j++) {
            float lo, hi;
            asm("mov.b64 {%0, %1}, %2;" : "=f"(lo), "=f"(hi) : "l"(acc[i][j]));
            const float z = (lo + hi) + bb[j];
            v[j] = 1.0f / (1.0f + expf(-z));
        }
        o.x = v[0]; o.y = v[1]; o.z = v[2]; o.w = v[3];
        *(float4*)&rates[(mBase + m0 + i) * NUM_NEURONS + nBase + n0] = o;
    }

#if __CUDA_ARCH__ >= 900
    cudaTriggerProgrammaticLaunchCompletion();
#endif
}

// ---------------------------------------------------------------------------
// Kernel B: streaming spike compare (R3 shape — measured 62.8us @74% DRAM).
// grid (T, BATCH), 256 threads; one (b,t) neuron row per block.
// u loads issued BEFORE the PDL dependency sync; rates read after.
// ---------------------------------------------------------------------------
__global__ __launch_bounds__(256)
void spike_kernel(const float4* __restrict__ u,
                  const float4* __restrict__ rates,
                  float4* __restrict__ spikes) {
    const int b = blockIdx.y;
    const long long base = (long long)(b * TIME_STEPS + blockIdx.x) * (NUM_NEURONS / 4);
    const int j = threadIdx.x * 2;

    const float4 u0 = __ldcs(&u[base + j]);
    const float4 u1 = __ldcs(&u[base + j + 1]);

#if __CUDA_ARCH__ >= 900
    cudaGridDependencySynchronize();
#endif

    const float4* rrow = rates + b * (NUM_NEURONS / 4);
    const float4 r0 = __ldg(&rrow[j]);
    const float4 r1 = __ldg(&rrow[j + 1]);

    float4 s0, s1;
    s0.x = (u0.x < r0.x) ? 1.0f : 0.0f;
    s0.y = (u0.y < r0.y) ? 1.0f : 0.0f;
    s0.z = (u0.z < r0.z) ? 1.0f : 0.0f;
    s0.w = (u0.w < r0.w) ? 1.0f : 0.0f;
    s1.x = (u1.x < r1.x) ? 1.0f : 0.0f;
    s1.y = (u1.y < r1.y) ? 1.0f : 0.0f;
    s1.z = (u1.z < r1.z) ? 1.0f : 0.0f;
    s1.w = (u1.w < r1.w) ? 1.0f : 0.0f;

    __stcs(&spikes[base + j], s0);
    __stcs(&spikes[base + j + 1], s1);
}

extern "C" void kernel_launch(void* const* d_in, const int* in_sizes, int n_in,
                              void* d_out, int out_size) {
    const float* x = (const float*)d_in[0];
    const float* W = (const float*)d_in[1];
    const float* b = (const float*)d_in[2];
    const float* u = (const float*)d_in[3];

    float* out    = (float*)d_out;
    float* spikes = out;                                               // 52,428,800
    float* rates  = out + (long long)BATCH * TIME_STEPS * NUM_NEURONS; // +524,288

    dim3 gridA(NUM_NEURONS / TBN, BATCH / TBM);   // (32, 4)
    rates_kernel<<<gridA, 128>>>(x, W, b, rates);

    const float4* u4 = (const float4*)u;
    const float4* r4 = (const float4*)rates;
    float4*       s4 = (float4*)spikes;

    cudaLaunchConfig_t cfg = {};
    cfg.gridDim  = dim3(TIME_STEPS, BATCH, 1);    // (100, 256)
    cfg.blockDim = dim3(256, 1, 1);
    cfg.dynamicSmemBytes = 0;
    cfg.stream = 0;
    cudaLaunchAttribute attrs[1];
    attrs[0].id = cudaLaunchAttributeProgrammaticStreamSerialization;
    attrs[0].val.programmaticStreamSerializationAllowed = 1;
    cfg.attrs = attrs;
    cfg.numAttrs = 1;

    cudaError_t e = cudaLaunchKernelEx(&cfg, spike_kernel, u4, r4, s4);
    if (e != cudaSuccess) {
        (void)cudaGetLastError();  // clear
        spike_kernel<<<dim3(TIME_STEPS, BATCH, 1), 256>>>(u4, r4, s4);
    }
}

// round 6
// speedup vs baseline: 1.1472x; 1.0140x over previous
#include <cuda_runtime.h>
#include <cuda_bf16.h>
#include <cstdint>

// SpikeEncoder: rates = sigmoid(x @ W^T + b); spikes = (u < rates)
// x: [256,512] f32, W: [2048,512] f32, b: [2048] f32, u: [256,100,2048] f32
// out: spikes [256*100*2048] f32, then rates [256*2048] f32

#define BATCH 256
#define INPUT_DIM 512
#define NUM_NEURONS 2048
#define TIME_STEPS 100

#define TBM 64
#define TBN 64
#define TBK 32
#define NTILES (INPUT_DIM / TBK)   // 16
#define NSTAGE 3

__device__ __forceinline__ void cp_async16(uint32_t smem_addr, const void* gmem) {
    asm volatile("cp.async.cg.shared.global [%0], [%1], 16;\n"
                 :: "r"(smem_addr), "l"(gmem));
}
__device__ __forceinline__ void cp_commit() {
    asm volatile("cp.async.commit_group;\n" ::: "memory");
}
__device__ __forceinline__ void cp_wait1() {
    asm volatile("cp.async.wait_group 1;\n" ::: "memory");
}

// Packed dual-FMA: acc.{lo,hi} += a.{lo,hi} * b.{lo,hi}
__device__ __forceinline__ void fma2(unsigned long long& acc,
                                     unsigned long long a,
                                     unsigned long long b) {
    asm("fma.rn.f32x2 %0, %1, %2, %0;" : "+l"(acc) : "l"(a), "l"(b));
}

// ---------------------------------------------------------------------------
// Kernel A: tiled fp32 GEMM (C = x @ W^T + b) -> sigmoid -> rates
// 64x64x32 tile, 256 threads (2 warps/SMSP for latency hiding), 8x2
// micro-tile. 3-stage cp.async pipeline (one tile always in flight).
// Swizzles chosen per-array so BOTH cooperative stores and fragment loads
// are bank-conflict-free:
//   A fragments: warp reads rows {0,8,...,56}+i  -> key (row>>3)&7 injective
//   B fragments: warp reads rows {8w,8w+2,8w+4,8w+6}+j -> key (row>>1)&7
// grid (32, 4) = 128 blocks.
// ---------------------------------------------------------------------------
__global__ __launch_bounds__(256)
void rates_kernel(const float* __restrict__ x,
                  const float* __restrict__ W,
                  const float* __restrict__ bias,
                  float* __restrict__ rates) {
    __shared__ float As[NSTAGE][TBM * TBK];   // 8KB per stage
    __shared__ float Bs[NSTAGE][TBN * TBK];   // 8KB per stage

    const int tid   = threadIdx.x;
    const int nBase = blockIdx.x * TBN;
    const int mBase = blockIdx.y * TBM;

    const int m0 = (tid & 7) * 8;    // 8 A rows per thread (stride-8 groups)
    const int n0 = (tid >> 3) * 2;   // 2 B rows per thread

    // Cooperative-load coords: 512 float4 per matrix per tile, 2 per thread.
    int lr[2], lc[2];
    uint32_t dstA[2], dstB[2];
    const uint32_t sA = (uint32_t)__cvta_generic_to_shared(&As[0][0]);
    const uint32_t sB = (uint32_t)__cvta_generic_to_shared(&Bs[0][0]);
#pragma unroll
    for (int l = 0; l < 2; l++) {
        const int f = tid + l * 256;        // 0..511
        lr[l] = f >> 3;                     // row 0..63
        lc[l] = f & 7;                      // k-chunk 0..7
        const int swA = lc[l] ^ ((lr[l] >> 3) & 7);
        const int swB = lc[l] ^ ((lr[l] >> 1) & 7);
        dstA[l] = sA + (uint32_t)(lr[l] * TBK + swA * 4) * 4u;
        dstB[l] = sB + (uint32_t)(lr[l] * TBK + swB * 4) * 4u;
    }
    const uint32_t stride = (uint32_t)(TBM * TBK) * 4u;

    // Issue stages 0 and 1
#pragma unroll
    for (int p = 0; p < 2; p++) {
        const int k0 = p * TBK;
        const uint32_t boff = (uint32_t)p * stride;
#pragma unroll
        for (int l = 0; l < 2; l++) {
            cp_async16(dstA[l] + boff, &x[(mBase + lr[l]) * INPUT_DIM + k0 + lc[l] * 4]);
            cp_async16(dstB[l] + boff, &W[(nBase + lr[l]) * INPUT_DIM + k0 + lc[l] * 4]);
        }
        cp_commit();
    }

    // Packed accumulators: acc[i][j] = (lo, hi) fp32 pair
    unsigned long long acc[8][2];
#pragma unroll
    for (int i = 0; i < 8; i++) { acc[i][0] = 0ull; acc[i][1] = 0ull; }

    int aRow[8], aSwz[8], bRow[2], bSwz[2];
#pragma unroll
    for (int i = 0; i < 8; i++) {
        aRow[i] = (m0 + i) * TBK;
        aSwz[i] = ((m0 + i) >> 3) & 7;
    }
#pragma unroll
    for (int j = 0; j < 2; j++) {
        bRow[j] = (n0 + j) * TBK;
        bSwz[j] = ((n0 + j) >> 1) & 7;
    }

    for (int t = 0; t < NTILES; t++) {
        cp_wait1();          // stage t landed (<=1 group still in flight)
        __syncthreads();     // all threads' copies visible; stage t-1 buf free

        if (t + 2 < NTILES) {
            const int k0 = (t + 2) * TBK;
            const uint32_t boff = (uint32_t)((t + 2) % NSTAGE) * stride;
#pragma unroll
            for (int l = 0; l < 2; l++) {
                cp_async16(dstA[l] + boff, &x[(mBase + lr[l]) * INPUT_DIM + k0 + lc[l] * 4]);
                cp_async16(dstB[l] + boff, &W[(nBase + lr[l]) * INPUT_DIM + k0 + lc[l] * 4]);
            }
            cp_commit();
        }

        const float* __restrict__ A = &As[t % NSTAGE][0];
        const float* __restrict__ B = &Bs[t % NSTAGE][0];

#pragma unroll
        for (int s = 0; s < 8; s++) {        // 4 k's per step (2 packed pairs)
            ulonglong2 av[8], bv[2];
#pragma unroll
            for (int i = 0; i < 8; i++)
                av[i] = *(const ulonglong2*)&A[aRow[i] + ((s ^ aSwz[i]) << 2)];
#pragma unroll
            for (int j = 0; j < 2; j++)
                bv[j] = *(const ulonglong2*)&B[bRow[j] + ((s ^ bSwz[j]) << 2)];

#pragma unroll
            for (int i = 0; i < 8; i++)
#pragma unroll
                for (int j = 0; j < 2; j++) {
                    fma2(acc[i][j], av[i].x, bv[j].x);
                    fma2(acc[i][j], av[i].y, bv[j].y);
                }
        }
    }

    // Epilogue: unpack (lo+hi) + bias + sigmoid, float2 stores
    const float2 b2 = *(const float2*)&bias[nBase + n0];
    const float bb[2] = {b2.x, b2.y};
#pragma unroll
    for (int i = 0; i < 8; i++) {
        float2 o;
        float v[2];
#pragma unroll
        for (int j = 0; j < 2; j++) {
            float lo, hi;
            asm("mov.b64 {%0, %1}, %2;" : "=f"(lo), "=f"(hi) : "l"(acc[i][j]));
            const float z = (lo + hi) + bb[j];
            v[j] = 1.0f / (1.0f + expf(-z));
        }
        o.x = v[0]; o.y = v[1];
        *(float2*)&rates[(mBase + m0 + i) * NUM_NEURONS + nBase + n0] = o;
    }

#if __CUDA_ARCH__ >= 900
    cudaTriggerProgrammaticLaunchCompletion();
#endif
}

// ---------------------------------------------------------------------------
// Kernel B: streaming spike compare (R3 shape — measured ~63us @74% DRAM).
// grid (T, BATCH), 256 threads; one (b,t) neuron row per block.
// ---------------------------------------------------------------------------
__global__ __launch_bounds__(256)
void spike_kernel(const float4* __restrict__ u,
                  const float4* __restrict__ rates,
                  float4* __restrict__ spikes) {
    const int b = blockIdx.y;
    const long long base = (long long)(b * TIME_STEPS + blockIdx.x) * (NUM_NEURONS / 4);
    const int j = threadIdx.x * 2;

    const float4 u0 = __ldcs(&u[base + j]);
    const float4 u1 = __ldcs(&u[base + j + 1]);

#if __CUDA_ARCH__ >= 900
    cudaGridDependencySynchronize();
#endif

    const float4* rrow = rates + b * (NUM_NEURONS / 4);
    const float4 r0 = __ldg(&rrow[j]);
    const float4 r1 = __ldg(&rrow[j + 1]);

    float4 s0, s1;
    s0.x = (u0.x < r0.x) ? 1.0f : 0.0f;
    s0.y = (u0.y < r0.y) ? 1.0f : 0.0f;
    s0.z = (u0.z < r0.z) ? 1.0f : 0.0f;
    s0.w = (u0.w < r0.w) ? 1.0f : 0.0f;
    s1.x = (u1.x < r1.x) ? 1.0f : 0.0f;
    s1.y = (u1.y < r1.y) ? 1.0f : 0.0f;
    s1.z = (u1.z < r1.z) ? 1.0f : 0.0f;
    s1.w = (u1.w < r1.w) ? 1.0f : 0.0f;

    __stcs(&spikes[base + j], s0);
    __stcs(&spikes[base + j + 1], s1);
}

extern "C" void kernel_launch(void* const* d_in, const int* in_sizes, int n_in,
                              void* d_out, int out_size) {
    const float* x = (const float*)d_in[0];
    const float* W = (const float*)d_in[1];
    const float* b = (const float*)d_in[2];
    const float* u = (const float*)d_in[3];

    float* out    = (float*)d_out;
    float* spikes = out;                                               // 52,428,800
    float* rates  = out + (long long)BATCH * TIME_STEPS * NUM_NEURONS; // +524,288

    dim3 gridA(NUM_NEURONS / TBN, BATCH / TBM);   // (32, 4)
    rates_kernel<<<gridA, 256>>>(x, W, b, rates);

    const float4* u4 = (const float4*)u;
    const float4* r4 = (const float4*)rates;
    float4*       s4 = (float4*)spikes;

    cudaLaunchConfig_t cfg = {};
    cfg.gridDim  = dim3(TIME_STEPS, BATCH, 1);    // (100, 256)
    cfg.blockDim = dim3(256, 1, 1);
    cfg.dynamicSmemBytes = 0;
    cfg.stream = 0;
    cudaLaunchAttribute attrs[1];
    attrs[0].id = cudaLaunchAttributeProgrammaticStreamSerialization;
    attrs[0].val.programmaticStreamSerializationAllowed = 1;
    cfg.attrs = attrs;
    cfg.numAttrs = 1;

    cudaError_t e = cudaLaunchKernelEx(&cfg, spike_kernel, u4, r4, s4);
    if (e != cudaSuccess) {
        (void)cudaGetLastError();  // clear
        spike_kernel<<<dim3(TIME_STEPS, BATCH, 1), 256>>>(u4, r4, s4);
    }
}

// round 8
// speedup vs baseline: 1.2133x; 1.0576x over previous
#include <cuda_runtime.h>
#include <cuda_bf16.h>
#include <cstdint>

// SpikeEncoder: rates = sigmoid(x @ W^T + b); spikes = (u < rates)
// x: [256,512] f32, W: [2048,512] f32, b: [2048] f32, u: [256,100,2048] f32
// out: spikes [256*100*2048] f32, then rates [256*2048] f32

#define BATCH 256
#define INPUT_DIM 512
#define NUM_NEURONS 2048
#define TIME_STEPS 100

#define TBM 64
#define TBN 64
#define TBK 32
#define NTILES (INPUT_DIM / TBK)   // 16

#define ROWF 36                    // padded floats per smem row (bank-bijective)
#define TILEF (64 * ROWF)          // 2304 floats per (matrix, component) tile
// smem buffer layout (floats): [buf][Ahi | Alo | Bhi | Blo], buf stride 4*TILEF
#define BUFF (4 * TILEF)           // 9216 floats
#define SMEM_BYTES (2 * BUFF * 4)  // 73728 bytes

// fp32 -> tf32 3-term split: v = hi + lo with |v - hi - lo| <= ~2^-22 |v|
__device__ __forceinline__ void tf32_split(float v, float& h, float& l) {
    uint32_t hb, lb;
    asm("cvt.rna.tf32.f32 %0, %1;" : "=r"(hb) : "f"(v));
    const float hf = __uint_as_float(hb);
    asm("cvt.rna.tf32.f32 %0, %1;" : "=r"(lb) : "f"(v - hf));
    h = hf;
    l = __uint_as_float(lb);
}

__device__ __forceinline__ void cvt_store(float* __restrict__ hi,
                                          float* __restrict__ lo,
                                          int off, float4 v) {
    float4 h, l;
    tf32_split(v.x, h.x, l.x);
    tf32_split(v.y, h.y, l.y);
    tf32_split(v.z, h.z, l.z);
    tf32_split(v.w, h.w, l.w);
    *(float4*)&hi[off] = h;
    *(float4*)&lo[off] = l;
}

// D += A(tf32, m16k8 row) x B(tf32, k8n8 col)
__device__ __forceinline__ void mma_tf32(float c[4],
                                         uint32_t a0, uint32_t a1,
                                         uint32_t a2, uint32_t a3,
                                         uint32_t b0, uint32_t b1) {
    asm volatile(
        "mma.sync.aligned.m16n8k8.row.col.f32.tf32.tf32.f32 "
        "{%0,%1,%2,%3}, {%4,%5,%6,%7}, {%8,%9}, {%0,%1,%2,%3};"
        : "+f"(c[0]), "+f"(c[1]), "+f"(c[2]), "+f"(c[3])
        : "r"(a0), "r"(a1), "r"(a2), "r"(a3), "r"(b0), "r"(b1));
}

// ---------------------------------------------------------------------------
// Kernel A: rates = sigmoid(x @ W^T + b) via tf32 tensor-core MMA with
// 3-term error compensation (xh*Wh + xh*Wl + xl*Wh), fp32 accumulators.
// 64x64 tile, 256 threads, 8 warps: warp = (mb = w&3)*16 rows x (nh = w>>2)*32
// cols (4 n8 blocks). K-tile 32 (4 k8 steps), double-buffered smem with
// inline tf32 split at store time. grid (32, 4).
// PLC trigger at kernel END (after rates stores): the spike grid's
// cudaGridDependencySynchronize must order AFTER the rates writes.
// ---------------------------------------------------------------------------
__global__ __launch_bounds__(256)
void rates_kernel(const float* __restrict__ x,
                  const float* __restrict__ W,
                  const float* __restrict__ bias,
                  float* __restrict__ rates) {
    extern __shared__ float sm[];

    const int tid  = threadIdx.x;
    const int warp = tid >> 5;
    const int lane = tid & 31;
    const int g = lane >> 2;       // group id (row within fragment)
    const int q = lane & 3;        // thread-in-group (k within fragment)
    const int mb = warp & 3;       // m16 block (0..3)
    const int nh = warp >> 2;      // n32 half (0..1)

    const int nBase = blockIdx.x * TBN;
    const int mBase = blockIdx.y * TBM;

    // Cooperative-load coords: 512 float4 per matrix per tile, 2 per thread
    int row[2], kc[2];
#pragma unroll
    for (int l = 0; l < 2; l++) {
        const int f = tid + l * 256;
        row[l] = f >> 3;           // 0..63
        kc[l]  = (f & 7) * 4;      // 0,4,...,28
    }

    // Prologue: tile 0 -> regs -> split -> smem buf 0
    float4 xa[2], wb[2];
#pragma unroll
    for (int l = 0; l < 2; l++) {
        xa[l] = *(const float4*)&x[(mBase + row[l]) * INPUT_DIM + kc[l]];
        wb[l] = *(const float4*)&W[(nBase + row[l]) * INPUT_DIM + kc[l]];
    }
    {
        float* Ahi = sm;            float* Alo = sm + TILEF;
        float* Bhi = sm + 2*TILEF;  float* Blo = sm + 3*TILEF;
#pragma unroll
        for (int l = 0; l < 2; l++) {
            const int off = row[l] * ROWF + kc[l];
            cvt_store(Ahi, Alo, off, xa[l]);
            cvt_store(Bhi, Blo, off, wb[l]);
        }
    }
    __syncthreads();

    float c[4][4];
#pragma unroll
    for (int nb = 0; nb < 4; nb++)
#pragma unroll
        for (int e = 0; e < 4; e++) c[nb][e] = 0.0f;

    const int ar0 = (mb * 16 + g) * ROWF;       // A fragment row g
    const int ar1 = ar0 + 8 * ROWF;             // A fragment row g+8

    for (int t = 0; t < NTILES; t++) {
        const float* base = sm + (t & 1) * BUFF;
        const float* Ahi = base;
        const float* Alo = base + TILEF;
        const float* Bhi = base + 2 * TILEF;
        const float* Blo = base + 3 * TILEF;

        // Prefetch next tile gmem -> regs (hidden behind MMA compute)
        if (t < NTILES - 1) {
            const int k0 = (t + 1) * TBK;
#pragma unroll
            for (int l = 0; l < 2; l++) {
                xa[l] = *(const float4*)&x[(mBase + row[l]) * INPUT_DIM + k0 + kc[l]];
                wb[l] = *(const float4*)&W[(nBase + row[l]) * INPUT_DIM + k0 + kc[l]];
            }
        }

#pragma unroll
        for (int s = 0; s < 4; s++) {           // 4 k8 steps per tile
            const int ka = s * 8 + q;
            const uint32_t a0h = __float_as_uint(Ahi[ar0 + ka]);
            const uint32_t a1h = __float_as_uint(Ahi[ar1 + ka]);
            const uint32_t a2h = __float_as_uint(Ahi[ar0 + ka + 4]);
            const uint32_t a3h = __float_as_uint(Ahi[ar1 + ka + 4]);
            const uint32_t a0l = __float_as_uint(Alo[ar0 + ka]);
            const uint32_t a1l = __float_as_uint(Alo[ar1 + ka]);
            const uint32_t a2l = __float_as_uint(Alo[ar0 + ka + 4]);
            const uint32_t a3l = __float_as_uint(Alo[ar1 + ka + 4]);

#pragma unroll
            for (int nb = 0; nb < 4; nb++) {
                const int rb = (nh * 32 + nb * 8 + g) * ROWF + ka;
                const uint32_t b0h = __float_as_uint(Bhi[rb]);
                const uint32_t b1h = __float_as_uint(Bhi[rb + 4]);
                const uint32_t b0l = __float_as_uint(Blo[rb]);
                const uint32_t b1l = __float_as_uint(Blo[rb + 4]);

                mma_tf32(c[nb], a0h, a1h, a2h, a3h, b0h, b1h);  // hi*hi
                mma_tf32(c[nb], a0h, a1h, a2h, a3h, b0l, b1l);  // hi*lo
                mma_tf32(c[nb], a0l, a1l, a2l, a3l, b0h, b1h);  // lo*hi
            }
        }

        // Split+store prefetched tile into the other buffer, then sync
        if (t < NTILES - 1) {
            float* nbuf = sm + ((t + 1) & 1) * BUFF;
            float* Ah = nbuf;            float* Al = nbuf + TILEF;
            float* Bh = nbuf + 2*TILEF;  float* Bl = nbuf + 3*TILEF;
#pragma unroll
            for (int l = 0; l < 2; l++) {
                const int off = row[l] * ROWF + kc[l];
                cvt_store(Ah, Al, off, xa[l]);
                cvt_store(Bh, Bl, off, wb[l]);
            }
            __syncthreads();
        }
    }

    // Epilogue: bias + sigmoid. c[nb]: {C[g][2q], C[g][2q+1], C[g+8][2q], C[g+8][2q+1]}
    const int m1 = mBase + mb * 16 + g;
    const int m2 = m1 + 8;
#pragma unroll
    for (int nb = 0; nb < 4; nb++) {
        const int col = nBase + nh * 32 + nb * 8 + 2 * q;
        const float2 bb = *(const float2*)&bias[col];

        float2 o1, o2;
        o1.x = 1.0f / (1.0f + expf(-(c[nb][0] + bb.x)));
        o1.y = 1.0f / (1.0f + expf(-(c[nb][1] + bb.y)));
        o2.x = 1.0f / (1.0f + expf(-(c[nb][2] + bb.x)));
        o2.y = 1.0f / (1.0f + expf(-(c[nb][3] + bb.y)));

        *(float2*)&rates[m1 * NUM_NEURONS + col] = o1;
        *(float2*)&rates[m2 * NUM_NEURONS + col] = o2;
    }

    // AFTER rates are written: release the dependent spike grid.
#if __CUDA_ARCH__ >= 900
    cudaTriggerProgrammaticLaunchCompletion();
#endif
}

// ---------------------------------------------------------------------------
// Kernel B: streaming spike compare (measured ~62.5us @74% DRAM — roofline).
// grid (T, BATCH), 256 threads; one (b,t) neuron row per block.
// u loads issued BEFORE the PDL dependency sync; rates read after.
// ---------------------------------------------------------------------------
__global__ __launch_bounds__(256)
void spike_kernel(const float4* __restrict__ u,
                  const float4* __restrict__ rates,
                  float4* __restrict__ spikes) {
    const int b = blockIdx.y;
    const long long base = (long long)(b * TIME_STEPS + blockIdx.x) * (NUM_NEURONS / 4);
    const int j = threadIdx.x * 2;

    const float4 u0 = __ldcs(&u[base + j]);
    const float4 u1 = __ldcs(&u[base + j + 1]);

#if __CUDA_ARCH__ >= 900
    cudaGridDependencySynchronize();
#endif

    const float4* rrow = rates + b * (NUM_NEURONS / 4);
    const float4 r0 = __ldg(&rrow[j]);
    const float4 r1 = __ldg(&rrow[j + 1]);

    float4 s0, s1;
    s0.x = (u0.x < r0.x) ? 1.0f : 0.0f;
    s0.y = (u0.y < r0.y) ? 1.0f : 0.0f;
    s0.z = (u0.z < r0.z) ? 1.0f : 0.0f;
    s0.w = (u0.w < r0.w) ? 1.0f : 0.0f;
    s1.x = (u1.x < r1.x) ? 1.0f : 0.0f;
    s1.y = (u1.y < r1.y) ? 1.0f : 0.0f;
    s1.z = (u1.z < r1.z) ? 1.0f : 0.0f;
    s1.w = (u1.w < r1.w) ? 1.0f : 0.0f;

    __stcs(&spikes[base + j], s0);
    __stcs(&spikes[base + j + 1], s1);
}

extern "C" void kernel_launch(void* const* d_in, const int* in_sizes, int n_in,
                              void* d_out, int out_size) {
    const float* x = (const float*)d_in[0];
    const float* W = (const float*)d_in[1];
    const float* b = (const float*)d_in[2];
    const float* u = (const float*)d_in[3];

    float* out    = (float*)d_out;
    float* spikes = out;                                               // 52,428,800
    float* rates  = out + (long long)BATCH * TIME_STEPS * NUM_NEURONS; // +524,288

    // Allow >48KB dynamic smem (host-side attribute; idempotent, capture-safe)
    cudaFuncSetAttribute(rates_kernel,
                         cudaFuncAttributeMaxDynamicSharedMemorySize, SMEM_BYTES);

    dim3 gridA(NUM_NEURONS / TBN, BATCH / TBM);   // (32, 4)
    rates_kernel<<<gridA, 256, SMEM_BYTES>>>(x, W, b, rates);

    const float4* u4 = (const float4*)u;
    const float4* r4 = (const float4*)rates;
    float4*       s4 = (float4*)spikes;

    cudaLaunchConfig_t cfg = {};
    cfg.gridDim  = dim3(TIME_STEPS, BATCH, 1);    // (100, 256)
    cfg.blockDim = dim3(256, 1, 1);
    cfg.dynamicSmemBytes = 0;
    cfg.stream = 0;
    cudaLaunchAttribute attrs[1];
    attrs[0].id = cudaLaunchAttributeProgrammaticStreamSerialization;
    attrs[0].val.programmaticStreamSerializationAllowed = 1;
    cfg.attrs = attrs;
    cfg.numAttrs = 1;

    cudaError_t e = cudaLaunchKernelEx(&cfg, spike_kernel, u4, r4, s4);
    if (e != cudaSuccess) {
        (void)cudaGetLastError();  // clear
        spike_kernel<<<dim3(TIME_STEPS, BATCH, 1), 256>>>(u4, r4, s4);
    }
}